// round 1
// baseline (speedup 1.0000x reference)
#include <cuda_runtime.h>
#include <cuda_bf16.h>

// AdderNet L1-conv: out[n,co,i,j] = -sum_{ci,kh,kw} |x_pad[n,ci,i+kh,j+kw] - W[co,ci,kh,kw]|
// x: (16,64,28,28) f32, W: (64,64,3,3) f32, stride=1, pad=1, out: (16,64,28,28) f32

#define N_   16
#define CI_  64
#define CO_  64
#define H_   28
#define W_   28

#define CO_T    16   // co per block
#define ROWS_T  8    // output rows per block
#define CI_CHUNK 16  // ci channels staged per iteration
#define THREADS (ROWS_T * W_)   // 224

__global__ __launch_bounds__(THREADS) void adder2d_kernel(
    const float* __restrict__ x,
    const float* __restrict__ w,
    float* __restrict__ out)
{
    // x tile: rows r0-1 .. r0+ROWS_T (10 rows), cols -1..28 (30 valid, stride 32)
    __shared__ float xs[CI_CHUNK][ROWS_T + 2][32];
    // w slice: co contiguous -> warp-broadcast reads
    __shared__ float ws[CI_CHUNK][9][CO_T];

    const int co0 = blockIdx.x * CO_T;
    const int r0  = blockIdx.y * ROWS_T;
    const int n   = blockIdx.z;

    const int tid = threadIdx.x;
    const int r = tid / W_;        // 0..7 local output row
    const int c = tid % W_;        // 0..27 local output col

    float acc[CO_T];
#pragma unroll
    for (int i = 0; i < CO_T; i++) acc[i] = 0.0f;

    const float* xn = x + (size_t)n * CI_ * H_ * W_;

    for (int ci0 = 0; ci0 < CI_; ci0 += CI_CHUNK) {
        __syncthreads();   // protect previous chunk's smem from overwrite

        // ---- stage x chunk: CI_CHUNK x 10 x 30 (zero-padded borders) ----
        for (int idx = tid; idx < CI_CHUNK * 10 * 30; idx += THREADS) {
            int ci  = idx / 300;
            int rem = idx % 300;
            int rr  = rem / 30;
            int cc  = rem % 30;
            int gr = r0 + rr - 1;
            int gc = cc - 1;
            float v = 0.0f;
            if (gr >= 0 && gr < H_ && gc >= 0 && gc < W_)
                v = xn[(ci0 + ci) * (H_ * W_) + gr * W_ + gc];
            xs[ci][rr][cc] = v;
        }

        // ---- stage w chunk: CI_CHUNK x 9 x CO_T ----
        for (int idx = tid; idx < CI_CHUNK * 9 * CO_T; idx += THREADS) {
            int co = idx % CO_T;
            int t  = idx / CO_T;
            int k  = t % 9;
            int ci = t / 9;
            ws[ci][k][co] = w[(size_t)(co0 + co) * (CI_ * 9) + (ci0 + ci) * 9 + k];
        }

        __syncthreads();

        // ---- compute ----
        for (int ci = 0; ci < CI_CHUNK; ci++) {
#pragma unroll
            for (int kh = 0; kh < 3; kh++) {
#pragma unroll
                for (int kw = 0; kw < 3; kw++) {
                    float xv = xs[ci][r + kh][c + kw];
#pragma unroll
                    for (int co = 0; co < CO_T; co++) {
                        acc[co] += fabsf(xv - ws[ci][kh * 3 + kw][co]);
                    }
                }
            }
        }
    }

    // ---- store ----
    const int gr = r0 + r;
    if (gr < H_) {
        float* op = out + ((size_t)n * CO_ + co0) * (H_ * W_) + gr * W_ + c;
#pragma unroll
        for (int co = 0; co < CO_T; co++) {
            op[(size_t)co * (H_ * W_)] = -acc[co];
        }
    }
}

extern "C" void kernel_launch(void* const* d_in, const int* in_sizes, int n_in,
                              void* d_out, int out_size)
{
    const float* x = (const float*)d_in[0];   // (16,64,28,28)
    const float* w = (const float*)d_in[1];   // (64,64,3,3)
    float* out = (float*)d_out;               // (16,64,28,28)

    dim3 grid(CO_ / CO_T, (H_ + ROWS_T - 1) / ROWS_T, N_);  // (4,4,16) = 256 blocks
    dim3 block(THREADS);                                     // 224
    adder2d_kernel<<<grid, block>>>(x, w, out);
}